// round 10
// baseline (speedup 1.0000x reference)
#include <cuda_runtime.h>
#include <cuda_fp16.h>
#include <math.h>
#include <stdint.h>

#define LQ   4096
#define CDIM 128
#define KNN  128
#define NH   4
#define DH   32
#define CP   16

__device__ float  g_q [LQ*CDIM];
__device__ __half g_kh[LQ*CDIM];
__device__ __half g_vh[LQ*CDIM];
__device__ float  g_g [LQ*CDIM];
__device__ float  g_ao[LQ*CDIM];

#define HSTRIDE 136          // fp16 tile row stride (halves)

__device__ __forceinline__ uint32_t smem_u32(const void* p) {
    uint32_t a;
    asm("{ .reg .u64 t; cvta.to.shared.u64 t, %1; cvt.u32.u64 %0, t; }"
        : "=r"(a) : "l"(p));
    return a;
}

#define LDMATRIX_X4(r0, r1, r2, r3, addr) \
    asm volatile("ldmatrix.sync.aligned.m8n8.x4.shared.b16 {%0,%1,%2,%3}, [%4];" \
                 : "=r"(r0), "=r"(r1), "=r"(r2), "=r"(r3) : "r"(addr))

#define MMA16816(d, a, b) \
    asm volatile("mma.sync.aligned.m16n8k16.row.col.f32.f16.f16.f32 " \
                 "{%0,%1,%2,%3}, {%4,%5,%6,%7}, {%8,%9}, {%0,%1,%2,%3};" \
                 : "+f"((d)[0]), "+f"((d)[1]), "+f"((d)[2]), "+f"((d)[3]) \
                 : "r"((a)[0]), "r"((a)[1]), "r"((a)[2]), "r"((a)[3]), \
                   "r"((b)[0]), "r"((b)[1]))

// ============================================================
// K1 (HMMA): fused rms(Q_L) + {q,k,v,g} projection + epilogues.
// 128 threads, 32-row tiles, grid(128, 4). 4 CTAs/SM.
// ============================================================
__global__ void __launch_bounds__(128, 4) qkvg_mma_kernel(
    const float* __restrict__ Q_L,
    const float* __restrict__ Wq, const float* __restrict__ Wk,
    const float* __restrict__ Wv, const float* __restrict__ Wg,
    const float* __restrict__ ln1,
    const float* __restrict__ lnq, const float* __restrict__ lnk)
{
    extern __shared__ __align__(16) char smc[];
    __half* Ah = (__half*)smc;                        // [32][136]
    __half* Bh = (__half*)(smc + 32*HSTRIDE*2);       // [128][136]
    __shared__ float ln1_s[CDIM];
    __shared__ float lnw_s[CDIM];
    __shared__ float ssred[32][5];

    const int midx = blockIdx.y;
    const float* W = (midx == 0) ? Wq : (midx == 1) ? Wk : (midx == 2) ? Wv : Wg;
    const int rowBase = blockIdx.x * 32;
    const int tid  = threadIdx.x;
    const int wid  = tid >> 5, lane = tid & 31;

    ln1_s[tid] = ln1[tid];
    lnw_s[tid] = (midx == 0) ? lnq[tid] : (midx == 1) ? lnk[tid] : 0.f;
    __syncthreads();

    // ---- stage A (rms'd fp16): 4 thr/row, 32 cols each ----
    {
        const int r = tid >> 2, q4 = tid & 3;
        const float4* xp = (const float4*)(Q_L + (size_t)(rowBase + r) * CDIM + q4 * 32);
        float4 xv[8];
        float ss = 0.f;
        #pragma unroll
        for (int i = 0; i < 8; i++) {
            xv[i] = xp[i];
            ss += xv[i].x*xv[i].x + xv[i].y*xv[i].y
                + xv[i].z*xv[i].z + xv[i].w*xv[i].w;
        }
        ss += __shfl_xor_sync(0xffffffffu, ss, 1);
        ss += __shfl_xor_sync(0xffffffffu, ss, 2);
        float s = rsqrtf(ss * (1.0f / CDIM) + 1e-5f);
        __half* ar = Ah + r * HSTRIDE + q4 * 32;
        #pragma unroll
        for (int i = 0; i < 8; i++) {
            int c = q4 * 32 + i * 4;
            __half2 h0 = __floats2half2_rn(xv[i].x*s*ln1_s[c+0], xv[i].y*s*ln1_s[c+1]);
            __half2 h1 = __floats2half2_rn(xv[i].z*s*ln1_s[c+2], xv[i].w*s*ln1_s[c+3]);
            uint2 u; u.x = *(unsigned*)&h0; u.y = *(unsigned*)&h1;
            *(uint2*)(ar + i * 4) = u;
        }
    }
    // ---- stage B = fp16(W); 1 thr/row, 128 cols ----
    {
        const float4* wp = (const float4*)(W + (size_t)tid * CDIM);
        __half* br = Bh + tid * HSTRIDE;
        #pragma unroll
        for (int i = 0; i < 32; i++) {
            float4 wv = wp[i];
            __half2 h0 = __floats2half2_rn(wv.x, wv.y);
            __half2 h1 = __floats2half2_rn(wv.z, wv.w);
            uint2 u; u.x = *(unsigned*)&h0; u.y = *(unsigned*)&h1;
            *(uint2*)(br + i * 4) = u;
        }
    }
    __syncthreads();

    // ---- mainloop: warp tile 32(m) x 32(n), wn = wid*32 ----
    const int wn = wid * 32;
    const uint32_t uA = smem_u32(Ah);
    const uint32_t uB = smem_u32(Bh);

    float d[2][4][4];
    #pragma unroll
    for (int mf = 0; mf < 2; mf++)
        #pragma unroll
        for (int nf = 0; nf < 4; nf++)
            #pragma unroll
            for (int e = 0; e < 4; e++) d[mf][nf][e] = 0.f;

    #pragma unroll
    for (int ks = 0; ks < 8; ks++) {
        const int kk = ks * 16;
        uint32_t a[2][4];
        #pragma unroll
        for (int mf = 0; mf < 2; mf++) {
            int row = mf * 16 + (lane & 15);
            int kc  = kk + ((lane >> 4) << 3);
            LDMATRIX_X4(a[mf][0], a[mf][1], a[mf][2], a[mf][3],
                        uA + (uint32_t)(row * HSTRIDE + kc) * 2);
        }
        uint32_t b[4][2];
        #pragma unroll
        for (int np = 0; np < 2; np++) {
            int row = wn + np * 16 + (lane & 7) + ((lane >> 4) << 3);
            int kc  = kk + ((lane & 8) ? 8 : 0);
            uint32_t r0, r1, r2, r3;
            LDMATRIX_X4(r0, r1, r2, r3, uB + (uint32_t)(row * HSTRIDE + kc) * 2);
            b[np*2][0]   = r0; b[np*2][1]   = r1;
            b[np*2+1][0] = r2; b[np*2+1][1] = r3;
        }
        #pragma unroll
        for (int mf = 0; mf < 2; mf++)
            #pragma unroll
            for (int nf = 0; nf < 4; nf++)
                MMA16816(d[mf][nf], a[mf], b[nf]);
    }

    const int g = lane >> 2, t = lane & 3;

    // ---- cross-warp sum-of-squares for row rms (q/k only) ----
    if (midx < 2) {
        #pragma unroll
        for (int mf = 0; mf < 2; mf++) {
            #pragma unroll
            for (int rh = 0; rh < 2; rh++) {
                float p = 0.f;
                #pragma unroll
                for (int nf = 0; nf < 4; nf++)
                    p += d[mf][nf][rh*2]*d[mf][nf][rh*2]
                       + d[mf][nf][rh*2+1]*d[mf][nf][rh*2+1];
                p += __shfl_xor_sync(0xffffffffu, p, 1);
                p += __shfl_xor_sync(0xffffffffu, p, 2);
                if (t == 0)
                    ssred[mf*16 + rh*8 + g][wid] = p;
            }
        }
    }
    __syncthreads();

    // ---- register-direct epilogue ----
    if (midx < 2) {
        #pragma unroll
        for (int mf = 0; mf < 2; mf++) {
            #pragma unroll
            for (int rh = 0; rh < 2; rh++) {
                int rloc = mf*16 + rh*8 + g;
                float sa = ssred[rloc][0] + ssred[rloc][1]
                         + ssred[rloc][2] + ssred[rloc][3];
                float s = rsqrtf(sa * (1.0f / CDIM) + 1e-5f);
                size_t orow = (size_t)(rowBase + rloc) * CDIM;
                #pragma unroll
                for (int nf = 0; nf < 4; nf++) {
                    int col = wn + nf*8 + t*2;
                    float v0 = d[mf][nf][rh*2]   * s * lnw_s[col];
                    float v1 = d[mf][nf][rh*2+1] * s * lnw_s[col+1];
                    if (midx == 0) {
                        float2 o = {v0, v1};
                        *(float2*)(g_q + orow + col) = o;
                    } else {
                        __half2 hv = __floats2half2_rn(v0, v1);
                        *(unsigned*)(g_kh + orow + col) = *(unsigned*)&hv;
                    }
                }
            }
        }
    } else if (midx == 2) {
        #pragma unroll
        for (int mf = 0; mf < 2; mf++)
            #pragma unroll
            for (int rh = 0; rh < 2; rh++) {
                size_t orow = (size_t)(rowBase + mf*16 + rh*8 + g) * CDIM;
                #pragma unroll
                for (int nf = 0; nf < 4; nf++) {
                    int col = wn + nf*8 + t*2;
                    __half2 hv = __floats2half2_rn(d[mf][nf][rh*2], d[mf][nf][rh*2+1]);
                    *(unsigned*)(g_vh + orow + col) = *(unsigned*)&hv;
                }
            }
    } else {
        #pragma unroll
        for (int mf = 0; mf < 2; mf++)
            #pragma unroll
            for (int rh = 0; rh < 2; rh++) {
                size_t orow = (size_t)(rowBase + mf*16 + rh*8 + g) * CDIM;
                #pragma unroll
                for (int nf = 0; nf < 4; nf++) {
                    int col = wn + nf*8 + t*2;
                    float2 o;
                    o.x = 1.0f / (1.0f + __expf(-d[mf][nf][rh*2]));
                    o.y = 1.0f / (1.0f + __expf(-d[mf][nf][rh*2+1]));
                    *(float2*)(g_g + orow + col) = o;
                }
            }
    }
}

// ============================================================
// K2: attention — LDG.128 everywhere. One block (256) per row.
// (unchanged from R9)
// ============================================================
__global__ void __launch_bounds__(256) attn_kernel(
    const float* __restrict__ P, const int* __restrict__ idxg,
    const float* __restrict__ Wb)
{
    __shared__ int   idx_s[KNN];
    __shared__ float q_s[CDIM];
    __shared__ float wb_s[NH*CP];
    __shared__ float bias_s[NH][KNN];
    __shared__ float sc[NH][KNN];
    __shared__ float av_red[16][CDIM];

    const int l = blockIdx.x;
    const int t = threadIdx.x;
    const int w = t >> 5, lane = t & 31;

    if (t < KNN) {
        idx_s[t] = idxg[(size_t)l * KNN + t];
        q_s[t]   = g_q[(size_t)l * CDIM + t] * 0.17677669529663687f;
    }
    if (t < NH*CP) wb_s[t] = Wb[t];
    __syncthreads();

    int jP = (w << 4) + (lane >> 1);
    int pp = lane & 1;
    const float* pr = P + ((size_t)l * LQ + idx_s[jP]) * CP + pp * 8;
    float4 p0 = ((const float4*)pr)[0];
    float4 p1 = ((const float4*)pr)[1];

    {
        const int half16 = lane >> 4;
        const int sub    = lane & 15;
        const int head   = sub >> 2;
        float qv[8];
        #pragma unroll
        for (int i = 0; i < 8; i++) qv[i] = q_s[sub * 8 + i];

        uint4 kb[8];
        int jb[8];
        #pragma unroll
        for (int r = 0; r < 8; r++) {
            jb[r] = (w << 4) + r * 2 + half16;
            kb[r] = *(const uint4*)(g_kh + (size_t)idx_s[jb[r]] * CDIM + sub * 8);
        }
        #pragma unroll
        for (int r = 0; r < 8; r++) {
            float2 a0 = __half22float2(*(__half2*)&kb[r].x);
            float2 a1 = __half22float2(*(__half2*)&kb[r].y);
            float2 a2 = __half22float2(*(__half2*)&kb[r].z);
            float2 a3 = __half22float2(*(__half2*)&kb[r].w);
            float d = qv[0]*a0.x + qv[1]*a0.y + qv[2]*a1.x + qv[3]*a1.y
                    + qv[4]*a2.x + qv[5]*a2.y + qv[6]*a3.x + qv[7]*a3.y;
            d += __shfl_xor_sync(0xffffffffu, d, 1);
            d += __shfl_xor_sync(0xffffffffu, d, 2);
            if ((lane & 3) == 0) sc[head][jb[r]] = d;
        }
    }

    {
        float pv[8] = {p0.x,p0.y,p0.z,p0.w, p1.x,p1.y,p1.z,p1.w};
        float b[NH];
        #pragma unroll
        for (int h = 0; h < NH; h++) {
            const float* wbp = &wb_s[h*CP + pp*8];
            b[h] = pv[0]*wbp[0] + pv[1]*wbp[1] + pv[2]*wbp[2] + pv[3]*wbp[3]
                 + pv[4]*wbp[4] + pv[5]*wbp[5] + pv[6]*wbp[6] + pv[7]*wbp[7];
        }
        #pragma unroll
        for (int h = 0; h < NH; h++) {
            b[h] += __shfl_xor_sync(0xffffffffu, b[h], 1);
            if (pp == 0) bias_s[h][jP] = b[h];
        }
    }
    __syncthreads();

    if (t < 128) {
        int h = w;
        float s0 = sc[h][lane]    + bias_s[h][lane];
        float s1 = sc[h][lane+32] + bias_s[h][lane+32];
        float s2 = sc[h][lane+64] + bias_s[h][lane+64];
        float s3 = sc[h][lane+96] + bias_s[h][lane+96];
        float mx = fmaxf(fmaxf(s0, s1), fmaxf(s2, s3));
        #pragma unroll
        for (int o = 16; o; o >>= 1) mx = fmaxf(mx, __shfl_xor_sync(0xffffffffu, mx, o));
        float e0 = __expf(s0 - mx), e1 = __expf(s1 - mx),
              e2 = __expf(s2 - mx), e3 = __expf(s3 - mx);
        float sum = e0 + e1 + e2 + e3;
        #pragma unroll
        for (int o = 16; o; o >>= 1) sum += __shfl_xor_sync(0xffffffffu, sum, o);
        float inv = 1.0f / sum;
        sc[h][lane]    = e0 * inv;
        sc[h][lane+32] = e1 * inv;
        sc[h][lane+64] = e2 * inv;
        sc[h][lane+96] = e3 * inv;
    }
    __syncthreads();

    {
        const int d8 = t & 15;
        const int jg = t >> 4;
        const int h  = d8 >> 2;
        uint4 vb[8];
        #pragma unroll
        for (int i = 0; i < 8; i++)
            vb[i] = *(const uint4*)(g_vh + (size_t)idx_s[jg*8 + i] * CDIM + d8 * 8);
        float acc[8] = {0,0,0,0,0,0,0,0};
        #pragma unroll
        for (int i = 0; i < 8; i++) {
            float p = sc[h][jg*8 + i];
            float2 v0 = __half22float2(*(__half2*)&vb[i].x);
            float2 v1 = __half22float2(*(__half2*)&vb[i].y);
            float2 v2 = __half22float2(*(__half2*)&vb[i].z);
            float2 v3 = __half22float2(*(__half2*)&vb[i].w);
            acc[0] += p*v0.x; acc[1] += p*v0.y;
            acc[2] += p*v1.x; acc[3] += p*v1.y;
            acc[4] += p*v2.x; acc[5] += p*v2.y;
            acc[6] += p*v3.x; acc[7] += p*v3.y;
        }
        float4 o0 = {acc[0], acc[1], acc[2], acc[3]};
        float4 o1 = {acc[4], acc[5], acc[6], acc[7]};
        *(float4*)&av_red[jg][d8*8]     = o0;
        *(float4*)&av_red[jg][d8*8 + 4] = o1;
    }
    __syncthreads();
    if (t < CDIM) {
        float o = 0.f;
        #pragma unroll
        for (int jg2 = 0; jg2 < 16; jg2++) o += av_red[jg2][t];
        o *= g_g[(size_t)l * CDIM + t];
        g_ao[(size_t)l * CDIM + t] = o;
    }
}

// ============================================================
// K3 (split-fp16 HMMA): out = g_ao @ Wo^T.
// CTA = 32m x 64n, grid(128, 2). Lighter frags, 2 CTAs/SM.
// ============================================================
__global__ void __launch_bounds__(256, 2) out_mma_kernel(
    const float* __restrict__ Wo, float* __restrict__ out)
{
    extern __shared__ __align__(16) char smc[];
    __half* Ah = (__half*)smc;                              // [32][136]
    __half* Al = (__half*)(smc + 32*HSTRIDE*2);
    __half* Wh = (__half*)(smc + 64*HSTRIDE*2);             // [64][136]
    __half* Wl = (__half*)(smc + (64+64)*HSTRIDE*2);

    const int rowBase = blockIdx.x * 32;
    const int colBase = blockIdx.y * 64;
    const int tid = threadIdx.x;
    const int wid = tid >> 5, lane = tid & 31;

    // stage A hi/lo: 8 thr/row, 16 cols each
    {
        const int r = tid >> 3, seg = tid & 7;
        const float4* xp = (const float4*)(g_ao + (size_t)(rowBase + r) * CDIM + seg * 16);
        #pragma unroll
        for (int i = 0; i < 4; i++) {
            float4 x = xp[i];
            float vv[4] = {x.x, x.y, x.z, x.w};
            __half hh[4], hl[4];
            #pragma unroll
            for (int e = 0; e < 4; e++) {
                hh[e] = __float2half_rn(vv[e]);
                hl[e] = __float2half_rn(vv[e] - __half2float(hh[e]));
            }
            int off = r * HSTRIDE + seg * 16 + i * 4;
            *(uint2*)(Ah + off) = *(uint2*)hh;
            *(uint2*)(Al + off) = *(uint2*)hl;
        }
    }
    // stage W hi/lo: 64 rows (colBase..+64), 4 thr/row, 32 cols
    {
        const int r = tid >> 2, q = tid & 3;
        const float4* wp = (const float4*)(Wo + (size_t)(colBase + r) * CDIM + q * 32);
        #pragma unroll
        for (int i = 0; i < 8; i++) {
            float4 x = wp[i];
            float vv[4] = {x.x, x.y, x.z, x.w};
            __half hh[4], hl[4];
            #pragma unroll
            for (int e = 0; e < 4; e++) {
                hh[e] = __float2half_rn(vv[e]);
                hl[e] = __float2half_rn(vv[e] - __half2float(hh[e]));
            }
            int off = r * HSTRIDE + q * 32 + i * 4;
            *(uint2*)(Wh + off) = *(uint2*)hh;
            *(uint2*)(Wl + off) = *(uint2*)hl;
        }
    }
    __syncthreads();

    // warp tile: 16m x 16n
    const int wm = (wid & 1) * 16;
    const int wn = (wid >> 1) * 16;
    const uint32_t uAh = smem_u32(Ah), uAl = smem_u32(Al);
    const uint32_t uWh = smem_u32(Wh), uWl = smem_u32(Wl);

    float d[2][4];
    #pragma unroll
    for (int nf = 0; nf < 2; nf++)
        #pragma unroll
        for (int e = 0; e < 4; e++) d[nf][e] = 0.f;

    #pragma unroll
    for (int ks = 0; ks < 8; ks++) {
        const int kk = ks * 16;
        uint32_t aoff = (uint32_t)((wm + (lane & 15)) * HSTRIDE
                                   + kk + ((lane >> 4) << 3)) * 2;
        uint32_t ah[4], al[4];
        LDMATRIX_X4(ah[0], ah[1], ah[2], ah[3], uAh + aoff);
        LDMATRIX_X4(al[0], al[1], al[2], al[3], uAl + aoff);
        uint32_t boff = (uint32_t)((wn + (lane & 7) + ((lane >> 4) << 3)) * HSTRIDE
                                   + kk + ((lane & 8) ? 8 : 0)) * 2;
        uint32_t bh[2][2], bl[2][2];
        {
            uint32_t r0, r1, r2, r3;
            LDMATRIX_X4(r0, r1, r2, r3, uWh + boff);
            bh[0][0] = r0; bh[0][1] = r1; bh[1][0] = r2; bh[1][1] = r3;
            LDMATRIX_X4(r0, r1, r2, r3, uWl + boff);
            bl[0][0] = r0; bl[0][1] = r1; bl[1][0] = r2; bl[1][1] = r3;
        }
        #pragma unroll
        for (int nf = 0; nf < 2; nf++) {
            MMA16816(d[nf], ah, bh[nf]);
            MMA16816(d[nf], al, bh[nf]);
            MMA16816(d[nf], ah, bl[nf]);
        }
    }

    const int g = lane >> 2, t = lane & 3;
    #pragma unroll
    for (int nf = 0; nf < 2; nf++) {
        int col = colBase + wn + nf*8 + t*2;
        size_t r0 = (size_t)(rowBase + wm + g) * CDIM + col;
        size_t r1 = (size_t)(rowBase + wm + g + 8) * CDIM + col;
        float2 o0 = {d[nf][0], d[nf][1]};
        float2 o1 = {d[nf][2], d[nf][3]};
        *(float2*)(out + r0) = o0;
        *(float2*)(out + r1) = o1;
    }
}

// ============================================================
extern "C" void kernel_launch(void* const* d_in, const int* in_sizes, int n_in,
                              void* d_out, int out_size)
{
    const float* Q_L  = (const float*)d_in[0];
    const float* P    = (const float*)d_in[1];
    const int*   idx  = (const int*)  d_in[2];
    const float* Wq   = (const float*)d_in[3];
    const float* Wk   = (const float*)d_in[4];
    const float* Wv   = (const float*)d_in[5];
    const float* Wg   = (const float*)d_in[6];
    const float* Wb   = (const float*)d_in[7];
    const float* Wo   = (const float*)d_in[8];
    const float* ln1  = (const float*)d_in[9];
    const float* lnq  = (const float*)d_in[10];
    const float* lnk  = (const float*)d_in[11];
    float* out = (float*)d_out;

    const int smem_qkvg = (32 + 128) * HSTRIDE * 2;          // 43.5 KB
    const int smem_out  = (32 + 32 + 64 + 64) * HSTRIDE * 2; // 52.2 KB
    cudaFuncSetAttribute(qkvg_mma_kernel,
        cudaFuncAttributeMaxDynamicSharedMemorySize, smem_qkvg);
    cudaFuncSetAttribute(out_mma_kernel,
        cudaFuncAttributeMaxDynamicSharedMemorySize, smem_out);

    dim3 g1(LQ/32, 4);
    qkvg_mma_kernel<<<g1, 128, smem_qkvg>>>(Q_L, Wq, Wk, Wv, Wg, ln1, lnq, lnk);
    attn_kernel<<<LQ, 256>>>(P, idx, Wb);
    dim3 g3(LQ/32, 2);
    out_mma_kernel<<<g3, 256, smem_out>>>(Wo, out);
}

// round 11
// speedup vs baseline: 1.1237x; 1.1237x over previous
#include <cuda_runtime.h>
#include <cuda_fp16.h>
#include <math.h>
#include <stdint.h>

#define LQ   4096
#define CDIM 128
#define KNN  128
#define NH   4
#define DH   32
#define CP   16

__device__ float  g_q [LQ*CDIM];
__device__ __half g_kh[LQ*CDIM];
__device__ __half g_vh[LQ*CDIM];
__device__ float  g_g [LQ*CDIM];
__device__ float  g_ao[LQ*CDIM];
__device__ __half g_wh [4*CDIM*CDIM];   // fp16 Wq,Wk,Wv,Wg
__device__ __half g_woh[CDIM*CDIM];     // Wo hi
__device__ __half g_wol[CDIM*CDIM];     // Wo lo

#define HSTRIDE 136          // fp16 tile row stride (halves)

__device__ __forceinline__ uint32_t smem_u32(const void* p) {
    uint32_t a;
    asm("{ .reg .u64 t; cvta.to.shared.u64 t, %1; cvt.u32.u64 %0, t; }"
        : "=r"(a) : "l"(p));
    return a;
}

#define LDMATRIX_X4(r0, r1, r2, r3, addr) \
    asm volatile("ldmatrix.sync.aligned.m8n8.x4.shared.b16 {%0,%1,%2,%3}, [%4];" \
                 : "=r"(r0), "=r"(r1), "=r"(r2), "=r"(r3) : "r"(addr))

#define MMA16816(d, a, b) \
    asm volatile("mma.sync.aligned.m16n8k16.row.col.f32.f16.f16.f32 " \
                 "{%0,%1,%2,%3}, {%4,%5,%6,%7}, {%8,%9}, {%0,%1,%2,%3};" \
                 : "+f"((d)[0]), "+f"((d)[1]), "+f"((d)[2]), "+f"((d)[3]) \
                 : "r"((a)[0]), "r"((a)[1]), "r"((a)[2]), "r"((a)[3]), \
                   "r"((b)[0]), "r"((b)[1]))

#define CP_ASYNC16(dst, src) \
    asm volatile("cp.async.cg.shared.global [%0], [%1], 16;" \
                 :: "r"(dst), "l"(src) : "memory")
#define CP_ASYNC_COMMIT() asm volatile("cp.async.commit_group;" ::: "memory")
#define CP_ASYNC_WAIT0()  asm volatile("cp.async.wait_group 0;" ::: "memory")

// ============================================================
// K0: one-time weight conversion. grid 80, 256 thr.
// blocks 0..63: Wq/Wk/Wv/Wg -> fp16. blocks 64..79: Wo -> hi/lo.
// ============================================================
__global__ void __launch_bounds__(256) wconv_kernel(
    const float* __restrict__ Wq, const float* __restrict__ Wk,
    const float* __restrict__ Wv, const float* __restrict__ Wg,
    const float* __restrict__ Wo)
{
    const int tid = threadIdx.x;
    if (blockIdx.x < 64) {
        int f = blockIdx.x * 256 + tid;        // float4 index, 0..16383
        int m = f >> 12, i = f & 4095;
        const float* Ws = (m == 0) ? Wq : (m == 1) ? Wk : (m == 2) ? Wv : Wg;
        float4 x = ((const float4*)Ws)[i];
        __half2 h0 = __floats2half2_rn(x.x, x.y);
        __half2 h1 = __floats2half2_rn(x.z, x.w);
        uint2 u; u.x = *(unsigned*)&h0; u.y = *(unsigned*)&h1;
        *(uint2*)(g_wh + m * CDIM*CDIM + i * 4) = u;
    } else {
        int i = (blockIdx.x - 64) * 256 + tid; // float4 index, 0..4095
        float4 x = ((const float4*)Wo)[i];
        float vv[4] = {x.x, x.y, x.z, x.w};
        __half hh[4], hl[4];
        #pragma unroll
        for (int e = 0; e < 4; e++) {
            hh[e] = __float2half_rn(vv[e]);
            hl[e] = __float2half_rn(vv[e] - __half2float(hh[e]));
        }
        *(uint2*)(g_woh + i * 4) = *(uint2*)hh;
        *(uint2*)(g_wol + i * 4) = *(uint2*)hl;
    }
}

// ============================================================
// K1 (HMMA): fused rms(Q_L) + {q,k,v,g} projection + epilogues.
// 64-row tiles, grid(64, 4), 256 thr (R9 shape) + cp.async B.
// ============================================================
__global__ void __launch_bounds__(256, 2) qkvg_mma_kernel(
    const float* __restrict__ Q_L,
    const float* __restrict__ ln1,
    const float* __restrict__ lnq, const float* __restrict__ lnk)
{
    extern __shared__ __align__(16) char smc[];
    __half* Ah = (__half*)smc;                        // [64][136]
    __half* Bh = (__half*)(smc + 64*HSTRIDE*2);       // [128][136]
    __shared__ float ln1_s[CDIM];
    __shared__ float lnw_s[CDIM];
    __shared__ float ssred[64][5];

    const int midx = blockIdx.y;
    const int rowBase = blockIdx.x * 64;
    const int tid  = threadIdx.x;
    const int wid  = tid >> 5, lane = tid & 31;

    // ---- issue B stage via cp.async FIRST (overlaps A compute) ----
    {
        const int r = tid >> 1, h = tid & 1;
        uint32_t dst = smem_u32(Bh + r * HSTRIDE + h * 64);
        const __half* src = g_wh + midx * CDIM*CDIM + r * CDIM + h * 64;
        #pragma unroll
        for (int i = 0; i < 8; i++)
            CP_ASYNC16(dst + i * 16, src + i * 8);
        CP_ASYNC_COMMIT();
    }

    if (tid < CDIM) {
        ln1_s[tid] = ln1[tid];
        lnw_s[tid] = (midx == 0) ? lnq[tid] : (midx == 1) ? lnk[tid] : 0.f;
    }

    // ---- stage A (rms'd fp16): 4 thr/row, 32 cols each ----
    {
        const int r = tid >> 2, q4 = tid & 3;
        const float4* xp = (const float4*)(Q_L + (size_t)(rowBase + r) * CDIM + q4 * 32);
        float4 xv[8];
        float ss = 0.f;
        #pragma unroll
        for (int i = 0; i < 8; i++) {
            xv[i] = xp[i];
            ss += xv[i].x*xv[i].x + xv[i].y*xv[i].y
                + xv[i].z*xv[i].z + xv[i].w*xv[i].w;
        }
        ss += __shfl_xor_sync(0xffffffffu, ss, 1);
        ss += __shfl_xor_sync(0xffffffffu, ss, 2);
        float s = rsqrtf(ss * (1.0f / CDIM) + 1e-5f);
        const float* lp = ln1 + q4 * 32;   // ln1_s may not be visible yet; read global
        __half* ar = Ah + r * HSTRIDE + q4 * 32;
        #pragma unroll
        for (int i = 0; i < 8; i++) {
            int c = i * 4;
            __half2 h0 = __floats2half2_rn(xv[i].x*s*__ldg(lp+c+0), xv[i].y*s*__ldg(lp+c+1));
            __half2 h1 = __floats2half2_rn(xv[i].z*s*__ldg(lp+c+2), xv[i].w*s*__ldg(lp+c+3));
            uint2 u; u.x = *(unsigned*)&h0; u.y = *(unsigned*)&h1;
            *(uint2*)(ar + i * 4) = u;
        }
    }
    CP_ASYNC_WAIT0();
    __syncthreads();

    // ---- mainloop: warp tile 32(m) x 32(n) ----
    const int wm = (wid & 1) * 32;
    const int wn = (wid >> 1) * 32;
    const uint32_t uA = smem_u32(Ah);
    const uint32_t uB = smem_u32(Bh);

    float d[2][4][4];
    #pragma unroll
    for (int mf = 0; mf < 2; mf++)
        #pragma unroll
        for (int nf = 0; nf < 4; nf++)
            #pragma unroll
            for (int e = 0; e < 4; e++) d[mf][nf][e] = 0.f;

    #pragma unroll
    for (int ks = 0; ks < 8; ks++) {
        const int kk = ks * 16;
        uint32_t a[2][4];
        #pragma unroll
        for (int mf = 0; mf < 2; mf++) {
            int row = wm + mf * 16 + (lane & 15);
            int kc  = kk + ((lane >> 4) << 3);
            LDMATRIX_X4(a[mf][0], a[mf][1], a[mf][2], a[mf][3],
                        uA + (uint32_t)(row * HSTRIDE + kc) * 2);
        }
        uint32_t b[4][2];
        #pragma unroll
        for (int np = 0; np < 2; np++) {
            int row = wn + np * 16 + (lane & 7) + ((lane >> 4) << 3);
            int kc  = kk + ((lane & 8) ? 8 : 0);
            uint32_t r0, r1, r2, r3;
            LDMATRIX_X4(r0, r1, r2, r3, uB + (uint32_t)(row * HSTRIDE + kc) * 2);
            b[np*2][0]   = r0; b[np*2][1]   = r1;
            b[np*2+1][0] = r2; b[np*2+1][1] = r3;
        }
        #pragma unroll
        for (int mf = 0; mf < 2; mf++)
            #pragma unroll
            for (int nf = 0; nf < 4; nf++)
                MMA16816(d[mf][nf], a[mf], b[nf]);
    }

    const int g = lane >> 2, t = lane & 3;

    if (midx < 2) {
        #pragma unroll
        for (int mf = 0; mf < 2; mf++) {
            #pragma unroll
            for (int rh = 0; rh < 2; rh++) {
                float p = 0.f;
                #pragma unroll
                for (int nf = 0; nf < 4; nf++)
                    p += d[mf][nf][rh*2]*d[mf][nf][rh*2]
                       + d[mf][nf][rh*2+1]*d[mf][nf][rh*2+1];
                p += __shfl_xor_sync(0xffffffffu, p, 1);
                p += __shfl_xor_sync(0xffffffffu, p, 2);
                if (t == 0)
                    ssred[wm + mf*16 + rh*8 + g][wid >> 1] = p;
            }
        }
    }
    __syncthreads();

    if (midx < 2) {
        #pragma unroll
        for (int mf = 0; mf < 2; mf++) {
            #pragma unroll
            for (int rh = 0; rh < 2; rh++) {
                int rloc = wm + mf*16 + rh*8 + g;
                float sa = ssred[rloc][0] + ssred[rloc][1]
                         + ssred[rloc][2] + ssred[rloc][3];
                float s = rsqrtf(sa * (1.0f / CDIM) + 1e-5f);
                size_t orow = (size_t)(rowBase + rloc) * CDIM;
                #pragma unroll
                for (int nf = 0; nf < 4; nf++) {
                    int col = wn + nf*8 + t*2;
                    float v0 = d[mf][nf][rh*2]   * s * lnw_s[col];
                    float v1 = d[mf][nf][rh*2+1] * s * lnw_s[col+1];
                    if (midx == 0) {
                        float2 o = {v0, v1};
                        *(float2*)(g_q + orow + col) = o;
                    } else {
                        __half2 hv = __floats2half2_rn(v0, v1);
                        *(unsigned*)(g_kh + orow + col) = *(unsigned*)&hv;
                    }
                }
            }
        }
    } else if (midx == 2) {
        #pragma unroll
        for (int mf = 0; mf < 2; mf++)
            #pragma unroll
            for (int rh = 0; rh < 2; rh++) {
                size_t orow = (size_t)(rowBase + wm + mf*16 + rh*8 + g) * CDIM;
                #pragma unroll
                for (int nf = 0; nf < 4; nf++) {
                    int col = wn + nf*8 + t*2;
                    __half2 hv = __floats2half2_rn(d[mf][nf][rh*2], d[mf][nf][rh*2+1]);
                    *(unsigned*)(g_vh + orow + col) = *(unsigned*)&hv;
                }
            }
    } else {
        #pragma unroll
        for (int mf = 0; mf < 2; mf++)
            #pragma unroll
            for (int rh = 0; rh < 2; rh++) {
                size_t orow = (size_t)(rowBase + wm + mf*16 + rh*8 + g) * CDIM;
                #pragma unroll
                for (int nf = 0; nf < 4; nf++) {
                    int col = wn + nf*8 + t*2;
                    float2 o;
                    o.x = 1.0f / (1.0f + __expf(-d[mf][nf][rh*2]));
                    o.y = 1.0f / (1.0f + __expf(-d[mf][nf][rh*2+1]));
                    *(float2*)(g_g + orow + col) = o;
                }
            }
    }
}

// ============================================================
// K2: attention — unchanged from R9 (LDG.128 everywhere).
// ============================================================
__global__ void __launch_bounds__(256) attn_kernel(
    const float* __restrict__ P, const int* __restrict__ idxg,
    const float* __restrict__ Wb)
{
    __shared__ int   idx_s[KNN];
    __shared__ float q_s[CDIM];
    __shared__ float wb_s[NH*CP];
    __shared__ float bias_s[NH][KNN];
    __shared__ float sc[NH][KNN];
    __shared__ float av_red[16][CDIM];

    const int l = blockIdx.x;
    const int t = threadIdx.x;
    const int w = t >> 5, lane = t & 31;

    if (t < KNN) {
        idx_s[t] = idxg[(size_t)l * KNN + t];
        q_s[t]   = g_q[(size_t)l * CDIM + t] * 0.17677669529663687f;
    }
    if (t < NH*CP) wb_s[t] = Wb[t];
    __syncthreads();

    int jP = (w << 4) + (lane >> 1);
    int pp = lane & 1;
    const float* pr = P + ((size_t)l * LQ + idx_s[jP]) * CP + pp * 8;
    float4 p0 = ((const float4*)pr)[0];
    float4 p1 = ((const float4*)pr)[1];

    {
        const int half16 = lane >> 4;
        const int sub    = lane & 15;
        const int head   = sub >> 2;
        float qv[8];
        #pragma unroll
        for (int i = 0; i < 8; i++) qv[i] = q_s[sub * 8 + i];

        uint4 kb[8];
        int jb[8];
        #pragma unroll
        for (int r = 0; r < 8; r++) {
            jb[r] = (w << 4) + r * 2 + half16;
            kb[r] = *(const uint4*)(g_kh + (size_t)idx_s[jb[r]] * CDIM + sub * 8);
        }
        #pragma unroll
        for (int r = 0; r < 8; r++) {
            float2 a0 = __half22float2(*(__half2*)&kb[r].x);
            float2 a1 = __half22float2(*(__half2*)&kb[r].y);
            float2 a2 = __half22float2(*(__half2*)&kb[r].z);
            float2 a3 = __half22float2(*(__half2*)&kb[r].w);
            float d = qv[0]*a0.x + qv[1]*a0.y + qv[2]*a1.x + qv[3]*a1.y
                    + qv[4]*a2.x + qv[5]*a2.y + qv[6]*a3.x + qv[7]*a3.y;
            d += __shfl_xor_sync(0xffffffffu, d, 1);
            d += __shfl_xor_sync(0xffffffffu, d, 2);
            if ((lane & 3) == 0) sc[head][jb[r]] = d;
        }
    }

    {
        float pv[8] = {p0.x,p0.y,p0.z,p0.w, p1.x,p1.y,p1.z,p1.w};
        float b[NH];
        #pragma unroll
        for (int h = 0; h < NH; h++) {
            const float* wbp = &wb_s[h*CP + pp*8];
            b[h] = pv[0]*wbp[0] + pv[1]*wbp[1] + pv[2]*wbp[2] + pv[3]*wbp[3]
                 + pv[4]*wbp[4] + pv[5]*wbp[5] + pv[6]*wbp[6] + pv[7]*wbp[7];
        }
        #pragma unroll
        for (int h = 0; h < NH; h++) {
            b[h] += __shfl_xor_sync(0xffffffffu, b[h], 1);
            if (pp == 0) bias_s[h][jP] = b[h];
        }
    }
    __syncthreads();

    if (t < 128) {
        int h = w;
        float s0 = sc[h][lane]    + bias_s[h][lane];
        float s1 = sc[h][lane+32] + bias_s[h][lane+32];
        float s2 = sc[h][lane+64] + bias_s[h][lane+64];
        float s3 = sc[h][lane+96] + bias_s[h][lane+96];
        float mx = fmaxf(fmaxf(s0, s1), fmaxf(s2, s3));
        #pragma unroll
        for (int o = 16; o; o >>= 1) mx = fmaxf(mx, __shfl_xor_sync(0xffffffffu, mx, o));
        float e0 = __expf(s0 - mx), e1 = __expf(s1 - mx),
              e2 = __expf(s2 - mx), e3 = __expf(s3 - mx);
        float sum = e0 + e1 + e2 + e3;
        #pragma unroll
        for (int o = 16; o; o >>= 1) sum += __shfl_xor_sync(0xffffffffu, sum, o);
        float inv = 1.0f / sum;
        sc[h][lane]    = e0 * inv;
        sc[h][lane+32] = e1 * inv;
        sc[h][lane+64] = e2 * inv;
        sc[h][lane+96] = e3 * inv;
    }
    __syncthreads();

    {
        const int d8 = t & 15;
        const int jg = t >> 4;
        const int h  = d8 >> 2;
        uint4 vb[8];
        #pragma unroll
        for (int i = 0; i < 8; i++)
            vb[i] = *(const uint4*)(g_vh + (size_t)idx_s[jg*8 + i] * CDIM + d8 * 8);
        float acc[8] = {0,0,0,0,0,0,0,0};
        #pragma unroll
        for (int i = 0; i < 8; i++) {
            float p = sc[h][jg*8 + i];
            float2 v0 = __half22float2(*(__half2*)&vb[i].x);
            float2 v1 = __half22float2(*(__half2*)&vb[i].y);
            float2 v2 = __half22float2(*(__half2*)&vb[i].z);
            float2 v3 = __half22float2(*(__half2*)&vb[i].w);
            acc[0] += p*v0.x; acc[1] += p*v0.y;
            acc[2] += p*v1.x; acc[3] += p*v1.y;
            acc[4] += p*v2.x; acc[5] += p*v2.y;
            acc[6] += p*v3.x; acc[7] += p*v3.y;
        }
        float4 o0 = {acc[0], acc[1], acc[2], acc[3]};
        float4 o1 = {acc[4], acc[5], acc[6], acc[7]};
        *(float4*)&av_red[jg][d8*8]     = o0;
        *(float4*)&av_red[jg][d8*8 + 4] = o1;
    }
    __syncthreads();
    if (t < CDIM) {
        float o = 0.f;
        #pragma unroll
        for (int jg2 = 0; jg2 < 16; jg2++) o += av_red[jg2][t];
        o *= g_g[(size_t)l * CDIM + t];
        g_ao[(size_t)l * CDIM + t] = o;
    }
}

// ============================================================
// K3 (split-fp16 HMMA): out = g_ao @ Wo^T. R8 shape (32m x 128n,
// grid 128) + cp.async W hi/lo from preconverted global.
// ============================================================
__global__ void __launch_bounds__(256) out_mma_kernel(float* __restrict__ out)
{
    extern __shared__ __align__(16) char smc[];
    __half* Ah = (__half*)smc;                              // [32][136]
    __half* Al = (__half*)(smc + 32*HSTRIDE*2);
    __half* Wh = (__half*)(smc + 64*HSTRIDE*2);             // [128][136]
    __half* Wl = (__half*)(smc + (64+128)*HSTRIDE*2);

    const int rowBase = blockIdx.x * 32;
    const int tid = threadIdx.x;
    const int wid = tid >> 5, lane = tid & 31;

    // issue W hi/lo cp.async first
    {
        const int r = tid >> 1, h = tid & 1;
        uint32_t dsth = smem_u32(Wh + r * HSTRIDE + h * 64);
        uint32_t dstl = smem_u32(Wl + r * HSTRIDE + h * 64);
        const __half* srch = g_woh + r * CDIM + h * 64;
        const __half* srcl = g_wol + r * CDIM + h * 64;
        #pragma unroll
        for (int i = 0; i < 8; i++) {
            CP_ASYNC16(dsth + i * 16, srch + i * 8);
            CP_ASYNC16(dstl + i * 16, srcl + i * 8);
        }
        CP_ASYNC_COMMIT();
    }

    // stage A hi/lo: 8 thr/row, 16 cols each
    {
        const int r = tid >> 3, seg = tid & 7;
        const float4* xp = (const float4*)(g_ao + (size_t)(rowBase + r) * CDIM + seg * 16);
        #pragma unroll
        for (int i = 0; i < 4; i++) {
            float4 x = xp[i];
            float vv[4] = {x.x, x.y, x.z, x.w};
            __half hh[4], hl[4];
            #pragma unroll
            for (int e = 0; e < 4; e++) {
                hh[e] = __float2half_rn(vv[e]);
                hl[e] = __float2half_rn(vv[e] - __half2float(hh[e]));
            }
            int off = r * HSTRIDE + seg * 16 + i * 4;
            *(uint2*)(Ah + off) = *(uint2*)hh;
            *(uint2*)(Al + off) = *(uint2*)hl;
        }
    }
    CP_ASYNC_WAIT0();
    __syncthreads();

    const int wm = (wid & 1) * 16;
    const int wn = (wid >> 1) * 32;
    const uint32_t uAh = smem_u32(Ah), uAl = smem_u32(Al);
    const uint32_t uWh = smem_u32(Wh), uWl = smem_u32(Wl);

    float d[4][4];
    #pragma unroll
    for (int nf = 0; nf < 4; nf++)
        #pragma unroll
        for (int e = 0; e < 4; e++) d[nf][e] = 0.f;

    #pragma unroll
    for (int ks = 0; ks < 8; ks++) {
        const int kk = ks * 16;
        uint32_t aoff = (uint32_t)((wm + (lane & 15)) * HSTRIDE
                                   + kk + ((lane >> 4) << 3)) * 2;
        uint32_t ah[4], al[4];
        LDMATRIX_X4(ah[0], ah[1], ah[2], ah[3], uAh + aoff);
        LDMATRIX_X4(al[0], al[1], al[2], al[3], uAl + aoff);
        uint32_t bh[4][2], bl[4][2];
        #pragma unroll
        for (int np = 0; np < 2; np++) {
            uint32_t boff = (uint32_t)((wn + np*16 + (lane & 7) + ((lane >> 4) << 3)) * HSTRIDE
                                       + kk + ((lane & 8) ? 8 : 0)) * 2;
            uint32_t r0, r1, r2, r3;
            LDMATRIX_X4(r0, r1, r2, r3, uWh + boff);
            bh[np*2][0] = r0; bh[np*2][1] = r1;
            bh[np*2+1][0] = r2; bh[np*2+1][1] = r3;
            LDMATRIX_X4(r0, r1, r2, r3, uWl + boff);
            bl[np*2][0] = r0; bl[np*2][1] = r1;
            bl[np*2+1][0] = r2; bl[np*2+1][1] = r3;
        }
        #pragma unroll
        for (int nf = 0; nf < 4; nf++) {
            MMA16816(d[nf], ah, bh[nf]);
            MMA16816(d[nf], al, bh[nf]);
            MMA16816(d[nf], ah, bl[nf]);
        }
    }

    const int g = lane >> 2, t = lane & 3;
    #pragma unroll
    for (int nf = 0; nf < 4; nf++) {
        int col = wn + nf*8 + t*2;
        size_t r0 = (size_t)(rowBase + wm + g) * CDIM + col;
        size_t r1 = (size_t)(rowBase + wm + g + 8) * CDIM + col;
        float2 o0 = {d[nf][0], d[nf][1]};
        float2 o1 = {d[nf][2], d[nf][3]};
        *(float2*)(out + r0) = o0;
        *(float2*)(out + r1) = o1;
    }
}

// ============================================================
extern "C" void kernel_launch(void* const* d_in, const int* in_sizes, int n_in,
                              void* d_out, int out_size)
{
    const float* Q_L  = (const float*)d_in[0];
    const float* P    = (const float*)d_in[1];
    const int*   idx  = (const int*)  d_in[2];
    const float* Wq   = (const float*)d_in[3];
    const float* Wk   = (const float*)d_in[4];
    const float* Wv   = (const float*)d_in[5];
    const float* Wg   = (const float*)d_in[6];
    const float* Wb   = (const float*)d_in[7];
    const float* Wo   = (const float*)d_in[8];
    const float* ln1  = (const float*)d_in[9];
    const float* lnq  = (const float*)d_in[10];
    const float* lnk  = (const float*)d_in[11];
    float* out = (float*)d_out;

    const int smem_qkvg = (64 + 128) * HSTRIDE * 2;
    const int smem_out  = (32 + 32 + 128 + 128) * HSTRIDE * 2;
    cudaFuncSetAttribute(qkvg_mma_kernel,
        cudaFuncAttributeMaxDynamicSharedMemorySize, smem_qkvg);
    cudaFuncSetAttribute(out_mma_kernel,
        cudaFuncAttributeMaxDynamicSharedMemorySize, smem_out);

    wconv_kernel<<<80, 256>>>(Wq, Wk, Wv, Wg, Wo);
    dim3 g1(LQ/64, 4);
    qkvg_mma_kernel<<<g1, 256, smem_qkvg>>>(Q_L, ln1, lnq, lnk);
    attn_kernel<<<LQ, 256>>>(P, idx, Wb);
    out_mma_kernel<<<LQ/32, 256, smem_out>>>(out);
}